// round 14
// baseline (speedup 1.0000x reference)
#include <cuda_runtime.h>
#include <cuda_bf16.h>
#include <cstdint>

#define B_ 4
#define N_ 8192
#define E_ 1024
#define D_ 64
#define M_ (B_*N_)          // 32768 rows of X
#define SPLITS 64
#define ROWS_PER_SPLIT (N_/SPLITS)   // 128
#define SCALE_ 0.21650635094610965f  // sqrt(3/64)

using u64 = unsigned long long;

// Scratch (device globals; no allocation allowed)
__device__ float g_K[M_*D_];
__device__ float g_V[M_*D_];
__device__ float g_epart[B_*SPLITS*D_*D_];
__device__ __nv_bfloat16 g_Qhi[M_*D_];
__device__ __nv_bfloat16 g_Qlo[M_*D_];
__device__ __nv_bfloat16 g_eThi[B_*D_*D_];    // [b][v][k] = scale*energy[k][v]
__device__ __nv_bfloat16 g_eTlo[B_*D_*D_];
__device__ __nv_bfloat16 g_Chi[M_*D_];        // context hi/lo
__device__ __nv_bfloat16 g_Clo[M_*D_];
__device__ __nv_bfloat16 g_Wb[192*E_];        // [n][k]: rows 0-63 wq, 64-127 wk, 128-191 wv
__device__ __nv_bfloat16 g_Wob[E_*D_];        // [e][v], exact bf16

// ---------------------------------------------------------------------------
// helpers
// ---------------------------------------------------------------------------
__device__ __forceinline__ void split2(float x, __nv_bfloat16& h, __nv_bfloat16& l) {
    h = __float2bfloat16_rn(x);
    l = __float2bfloat16_rn(x - __bfloat162float(h));
}

__device__ __forceinline__ uint2 split_pack4(float4 v, uint2& lo_out) {
    __nv_bfloat16 h0,l0,h1,l1,h2,l2,h3,l3;
    split2(v.x, h0, l0); split2(v.y, h1, l1);
    split2(v.z, h2, l2); split2(v.w, h3, l3);
    __nv_bfloat162 p01 = __halves2bfloat162(h0, h1);
    __nv_bfloat162 p23 = __halves2bfloat162(h2, h3);
    __nv_bfloat162 q01 = __halves2bfloat162(l0, l1);
    __nv_bfloat162 q23 = __halves2bfloat162(l2, l3);
    uint2 hi; hi.x = *(unsigned*)&p01; hi.y = *(unsigned*)&p23;
    lo_out.x = *(unsigned*)&q01; lo_out.y = *(unsigned*)&q23;
    return hi;
}

// packed f32x2 (sm_100+): two IEEE fp32 FMAs per instruction
__device__ __forceinline__ u64 pack2(float lo, float hi) {
    u64 r; asm("mov.b64 %0, {%1, %2};" : "=l"(r) : "f"(lo), "f"(hi)); return r;
}
__device__ __forceinline__ void unpack2(u64 v, float& lo, float& hi) {
    asm("mov.b64 {%0, %1}, %2;" : "=f"(lo), "=f"(hi) : "l"(v));
}
__device__ __forceinline__ u64 ffma2(u64 a, u64 b, u64 c) {
    u64 d; asm("fma.rn.f32x2 %0, %1, %2, %3;" : "=l"(d) : "l"(a), "l"(b), "l"(c)); return d;
}

// D(16x8,f32) += A(16x16,bf16,row) * B(16x8,bf16,col)
__device__ __forceinline__ void mma16816(float* d, const unsigned* a, const unsigned* b) {
    asm volatile(
        "mma.sync.aligned.m16n8k16.row.col.f32.bf16.bf16.f32 "
        "{%0,%1,%2,%3}, {%4,%5,%6,%7}, {%8,%9}, {%0,%1,%2,%3};\n"
        : "+f"(d[0]), "+f"(d[1]), "+f"(d[2]), "+f"(d[3])
        : "r"(a[0]), "r"(a[1]), "r"(a[2]), "r"(a[3]), "r"(b[0]), "r"(b[1]));
}

__device__ __forceinline__ void ldmx4(unsigned* r, const void* p) {
    unsigned a = (unsigned)__cvta_generic_to_shared(p);
    asm volatile("ldmatrix.sync.aligned.m8n8.x4.shared.b16 {%0,%1,%2,%3}, [%4];"
        : "=r"(r[0]), "=r"(r[1]), "=r"(r[2]), "=r"(r[3]) : "r"(a));
}

// ---------------------------------------------------------------------------
// K0a: pre-convert qkv weights to bf16 (exact: +-2^-5), layout [n][k].
// ---------------------------------------------------------------------------
__global__ __launch_bounds__(256) void wconv_kernel(
    const float* __restrict__ Wq, const float* __restrict__ Wk, const float* __restrict__ Wv)
{
    int i = blockIdx.x * 256 + threadIdx.x;
    int n = i >> 8;
    int g = i & 255;
    const float* W = (n < 64) ? Wq : (n < 128 ? Wk : Wv);
    int rr = n & 63;
    float4 v = *(const float4*)&W[(size_t)rr * E_ + g * 4];
    __nv_bfloat162 p01 = __halves2bfloat162(__float2bfloat16_rn(v.x), __float2bfloat16_rn(v.y));
    __nv_bfloat162 p23 = __halves2bfloat162(__float2bfloat16_rn(v.z), __float2bfloat16_rn(v.w));
    uint2 u; u.x = *(unsigned*)&p01; u.y = *(unsigned*)&p23;
    *(uint2*)&g_Wb[(size_t)n * E_ + g * 4] = u;
}

// K0b: pre-convert wo to bf16 (exact: +-2^-3).  [E][64] row-major.
__global__ __launch_bounds__(256) void woconv_kernel(const float* __restrict__ Wo)
{
    int i = blockIdx.x * 256 + threadIdx.x;
    int r = i >> 4, g = i & 15;
    float4 v = *(const float4*)&Wo[(size_t)r * D_ + g * 4];
    __nv_bfloat162 p01 = __halves2bfloat162(__float2bfloat16_rn(v.x), __float2bfloat16_rn(v.y));
    __nv_bfloat162 p23 = __halves2bfloat162(__float2bfloat16_rn(v.z), __float2bfloat16_rn(v.w));
    uint2 u; u.x = *(unsigned*)&p01; u.y = *(unsigned*)&p23;
    *(uint2*)&g_Wob[(size_t)r * D_ + g * 4] = u;
}

// ---------------------------------------------------------------------------
// K1: fused QKV projection, legacy bf16 MMA.  BK 32 -> 64: halves barrier
// count (32 chunks -> 16) and loop overhead.  smem 46KB static (<=48KB);
// 144B row stride (9*16B, odd) keeps ldmatrix conflict-free.
// BM=64, BN=192, 8 warps (2m x 4n), warp tile 32m x 48n.
// X split bf16 hi/lo -> 2 MMA products (weights exact in bf16).
// ---------------------------------------------------------------------------
#define BKQ 64
__global__ __launch_bounds__(256) void qkv_mma_kernel(const float* __restrict__ X)
{
    __shared__ __nv_bfloat16 Xh[64][BKQ + 8];   // 144B row stride
    __shared__ __nv_bfloat16 Xl[64][BKQ + 8];
    __shared__ __nv_bfloat16 Wb[192][BKQ + 8];

    const int m0   = blockIdx.x * 64;
    const int tid  = threadIdx.x;
    const int warp = tid >> 5, lane = tid & 31;
    const int wm = warp >> 2, wn = warp & 3;
    const int lr = lane >> 2, lc = (lane & 3) * 2;

    float acc[2][6][4];
    #pragma unroll
    for (int i = 0; i < 2; i++)
        #pragma unroll
        for (int j = 0; j < 6; j++)
            #pragma unroll
            for (int q = 0; q < 4; q++) acc[i][j][q] = 0.f;

    // prefetch chunk 0: X 64x64 fp32 = 1024 float4 (4/thr);
    // W 192x64 bf16 = 1536 uint4 (6/thr)
    float4 xv[4];
    uint4  wvb[6];
    #pragma unroll
    for (int t = 0; t < 4; t++) {
        int idx = t * 256 + tid;
        int r = idx >> 4, c = idx & 15;
        xv[t] = *(const float4*)&X[(size_t)(m0 + r) * E_ + c * 4];
    }
    #pragma unroll
    for (int t = 0; t < 6; t++) {
        int idx = t * 256 + tid;
        int r = idx >> 3, q = idx & 7;
        wvb[t] = *(const uint4*)&g_Wb[(size_t)r * E_ + q * 8];
    }

    for (int k0 = 0; k0 < E_; k0 += BKQ) {
        #pragma unroll
        for (int t = 0; t < 4; t++) {
            int idx = t * 256 + tid;
            int r = idx >> 4, c = idx & 15;
            uint2 lo;
            uint2 hi = split_pack4(xv[t], lo);
            *(uint2*)&Xh[r][c * 4] = hi;
            *(uint2*)&Xl[r][c * 4] = lo;
        }
        #pragma unroll
        for (int t = 0; t < 6; t++) {
            int idx = t * 256 + tid;
            int r = idx >> 3, q = idx & 7;
            *(uint4*)&Wb[r][q * 8] = wvb[t];
        }
        __syncthreads();

        if (k0 + BKQ < E_) {
            int kn = k0 + BKQ;
            #pragma unroll
            for (int t = 0; t < 4; t++) {
                int idx = t * 256 + tid;
                int r = idx >> 4, c = idx & 15;
                xv[t] = *(const float4*)&X[(size_t)(m0 + r) * E_ + kn + c * 4];
            }
            #pragma unroll
            for (int t = 0; t < 6; t++) {
                int idx = t * 256 + tid;
                int r = idx >> 3, q = idx & 7;
                wvb[t] = *(const uint4*)&g_Wb[(size_t)r * E_ + kn + q * 8];
            }
        }

        #pragma unroll
        for (int ks = 0; ks < BKQ; ks += 16) {
            unsigned bf[6][2];
            #pragma unroll
            for (int np = 0; np < 3; np++) {
                int n0 = wn * 48 + np * 16;
                const __nv_bfloat16* p =
                    &Wb[n0 + ((lane >> 4) << 3) + (lane & 7)][ks + (((lane >> 3) & 1) << 3)];
                unsigned t4[4];
                ldmx4(t4, p);
                bf[np*2][0] = t4[0]; bf[np*2][1] = t4[1];
                bf[np*2+1][0] = t4[2]; bf[np*2+1][1] = t4[3];
            }
            #pragma unroll
            for (int mt = 0; mt < 2; mt++) {
                int r0 = wm * 32 + mt * 16;
                unsigned ah[4], al[4];
                ldmx4(ah, &Xh[r0 + (lane & 15)][ks + ((lane >> 4) << 3)]);
                ldmx4(al, &Xl[r0 + (lane & 15)][ks + ((lane >> 4) << 3)]);
                #pragma unroll
                for (int nt = 0; nt < 6; nt++) mma16816(acc[mt][nt], ah, bf[nt]);
                #pragma unroll
                for (int nt = 0; nt < 6; nt++) mma16816(acc[mt][nt], al, bf[nt]);
            }
        }
        __syncthreads();
    }

    // Epilogue: fragment n-range selects Q / K / V (8 | 64, never crosses)
    #pragma unroll
    for (int mt = 0; mt < 2; mt++)
        #pragma unroll
        for (int nt = 0; nt < 6; nt++) {
            int ng  = wn * 48 + nt * 8;
            int sel = ng >> 6;
            int col = (ng & 63) + lc;
            int row = m0 + wm * 32 + mt * 16 + lr;
            if (sel == 0) {
                __nv_bfloat16 h0,l0,h1,l1;
                split2(acc[mt][nt][0], h0, l0); split2(acc[mt][nt][1], h1, l1);
                *(__nv_bfloat162*)&g_Qhi[(size_t)row * D_ + col] = __halves2bfloat162(h0, h1);
                *(__nv_bfloat162*)&g_Qlo[(size_t)row * D_ + col] = __halves2bfloat162(l0, l1);
                split2(acc[mt][nt][2], h0, l0); split2(acc[mt][nt][3], h1, l1);
                *(__nv_bfloat162*)&g_Qhi[(size_t)(row + 8) * D_ + col] = __halves2bfloat162(h0, h1);
                *(__nv_bfloat162*)&g_Qlo[(size_t)(row + 8) * D_ + col] = __halves2bfloat162(l0, l1);
            } else {
                float* Out = (sel == 1) ? g_K : g_V;
                *(float2*)&Out[(size_t)row * D_ + col] =
                    make_float2(acc[mt][nt][0], acc[mt][nt][1]);
                *(float2*)&Out[(size_t)(row + 8) * D_ + col] =
                    make_float2(acc[mt][nt][2], acc[mt][nt][3]);
            }
        }
}

// ---------------------------------------------------------------------------
// K2: energy partials, fp32 SIMT with packed FFMA2 + 32-row tiles.
// ---------------------------------------------------------------------------
__global__ __launch_bounds__(256) void energy_kernel()
{
    const int s = blockIdx.x;
    const int b = blockIdx.y;
    const float* Kb = g_K + (size_t)b * N_ * D_;
    const float* Vb = g_V + (size_t)b * N_ * D_;
    const int n_base = s * ROWS_PER_SPLIT;

    __shared__ float Ks[32][D_];
    __shared__ float Vs[32][D_];

    const int tid = threadIdx.x;
    const int ty  = tid >> 4;
    const int tx  = tid & 15;

    u64 acc[4][2];
    #pragma unroll
    for (int i = 0; i < 4; i++) { acc[i][0] = 0ull; acc[i][1] = 0ull; }

    for (int c = 0; c < ROWS_PER_SPLIT; c += 32) {
        #pragma unroll
        for (int t = 0; t < 2; t++) {
            int idx = t * 256 + tid;
            int r  = idx >> 4;
            int c4 = idx & 15;
            *(float4*)&Ks[r][c4 * 4] = *(const float4*)&Kb[(size_t)(n_base + c + r) * D_ + c4 * 4];
            *(float4*)&Vs[r][c4 * 4] = *(const float4*)&Vb[(size_t)(n_base + c + r) * D_ + c4 * 4];
        }
        __syncthreads();
        #pragma unroll
        for (int n = 0; n < 32; n++) {
            float4 kv = *(const float4*)&Ks[n][ty * 4];
            ulonglong2 vv = *(const ulonglong2*)&Vs[n][tx * 4];
            u64 kd[4] = { pack2(kv.x, kv.x), pack2(kv.y, kv.y),
                          pack2(kv.z, kv.z), pack2(kv.w, kv.w) };
            #pragma unroll
            for (int i = 0; i < 4; i++) {
                acc[i][0] = ffma2(kd[i], vv.x, acc[i][0]);
                acc[i][1] = ffma2(kd[i], vv.y, acc[i][1]);
            }
        }
        __syncthreads();
    }

    float* ep = g_epart + ((size_t)(b * SPLITS + s)) * (D_ * D_);
    #pragma unroll
    for (int i = 0; i < 4; i++) {
        float e0, e1, e2, e3;
        unpack2(acc[i][0], e0, e1);
        unpack2(acc[i][1], e2, e3);
        *(float4*)&ep[(ty * 4 + i) * D_ + tx * 4] = make_float4(e0, e1, e2, e3);
    }
}

// ---------------------------------------------------------------------------
// K3: reduce epart over 64 splits -> scaled eT[v][k] as bf16 hi/lo.
// ---------------------------------------------------------------------------
__global__ __launch_bounds__(256) void ereduce_kernel()
{
    const int b = blockIdx.y;
    const int base = blockIdx.x * 256 + threadIdx.x;   // 0..4095 = k*64+v
    const float* ep = g_epart + (size_t)b * SPLITS * D_ * D_ + base;
    float s = 0.f;
    #pragma unroll
    for (int sp = 0; sp < SPLITS; sp++)
        s += ep[(size_t)sp * (D_ * D_)];
    s *= SCALE_;
    int k = base >> 6;
    int v = base & 63;
    __nv_bfloat16 h, l;
    split2(s, h, l);
    g_eThi[(size_t)b * D_ * D_ + v * D_ + k] = h;
    g_eTlo[(size_t)b * D_ * D_ + v * D_ + k] = l;
}

// ---------------------------------------------------------------------------
// K4: context[m][v] = sum_k Q[m][k] * (scale*energy)[k][v] on tensor cores.
// 3-product split: Qh*Eh + Qh*El + Ql*Eh.  BM=128, BN=64, BK=32.
// ---------------------------------------------------------------------------
__global__ __launch_bounds__(256) void context_kernel()
{
    __shared__ __nv_bfloat16 Qh[128][40];
    __shared__ __nv_bfloat16 Ql[128][40];
    __shared__ __nv_bfloat16 Eh[64][40];
    __shared__ __nv_bfloat16 El[64][40];

    const int m0 = blockIdx.x * 128;
    const int b  = m0 >> 13;
    const size_t eb = (size_t)b * D_ * D_;
    const int tid  = threadIdx.x;
    const int warp = tid >> 5, lane = tid & 31;
    const int wm = warp >> 1, wn = warp & 1;
    const int lr = lane >> 2, lc = (lane & 3) * 2;

    float acc[2][4][4];
    #pragma unroll
    for (int i = 0; i < 2; i++)
        #pragma unroll
        for (int j = 0; j < 4; j++)
            #pragma unroll
            for (int q = 0; q < 4; q++) acc[i][j][q] = 0.f;

    for (int k0 = 0; k0 < D_; k0 += 32) {
        #pragma unroll
        for (int t = 0; t < 4; t++) {
            int idx = t * 256 + tid;
            int r = idx >> 3, c = idx & 7;
            *(uint2*)&Qh[r][c * 4] = *(const uint2*)&g_Qhi[(size_t)(m0 + r) * D_ + k0 + c * 4];
            *(uint2*)&Ql[r][c * 4] = *(const uint2*)&g_Qlo[(size_t)(m0 + r) * D_ + k0 + c * 4];
        }
        #pragma unroll
        for (int t = 0; t < 2; t++) {
            int idx = t * 256 + tid;
            int r = idx >> 3, c = idx & 7;
            *(uint2*)&Eh[r][c * 4] = *(const uint2*)&g_eThi[eb + (size_t)r * D_ + k0 + c * 4];
            *(uint2*)&El[r][c * 4] = *(const uint2*)&g_eTlo[eb + (size_t)r * D_ + k0 + c * 4];
        }
        __syncthreads();

        #pragma unroll
        for (int ks = 0; ks < 32; ks += 16) {
            unsigned bh[4][2], bl[4][2];
            #pragma unroll
            for (int np = 0; np < 2; np++) {
                int nrow = wn * 32 + np * 16 + ((lane >> 4) << 3) + (lane & 7);
                int ncol = ks + (((lane >> 3) & 1) << 3);
                unsigned t4[4];
                ldmx4(t4, &Eh[nrow][ncol]);
                bh[np*2][0] = t4[0]; bh[np*2][1] = t4[1];
                bh[np*2+1][0] = t4[2]; bh[np*2+1][1] = t4[3];
                ldmx4(t4, &El[nrow][ncol]);
                bl[np*2][0] = t4[0]; bl[np*2][1] = t4[1];
                bl[np*2+1][0] = t4[2]; bl[np*2+1][1] = t4[3];
            }
            #pragma unroll
            for (int mt = 0; mt < 2; mt++) {
                int r0 = wm * 32 + mt * 16;
                unsigned ah[4], al[4];
                ldmx4(ah, &Qh[r0 + (lane & 15)][ks + ((lane >> 4) << 3)]);
                ldmx4(al, &Ql[r0 + (lane & 15)][ks + ((lane >> 4) << 3)]);
                #pragma unroll
                for (int nt = 0; nt < 4; nt++) mma16816(acc[mt][nt], ah, bh[nt]);
                #pragma unroll
                for (int nt = 0; nt < 4; nt++) mma16816(acc[mt][nt], ah, bl[nt]);
                #pragma unroll
                for (int nt = 0; nt < 4; nt++) mma16816(acc[mt][nt], al, bh[nt]);
            }
        }
        __syncthreads();
    }

    #pragma unroll
    for (int mt = 0; mt < 2; mt++)
        #pragma unroll
        for (int nt = 0; nt < 4; nt++) {
            int row = m0 + wm * 32 + mt * 16 + lr;
            int col = wn * 32 + nt * 8 + lc;
            __nv_bfloat16 h0,l0,h1,l1;
            split2(acc[mt][nt][0], h0, l0); split2(acc[mt][nt][1], h1, l1);
            *(__nv_bfloat162*)&g_Chi[(size_t)row * D_ + col] = __halves2bfloat162(h0, h1);
            *(__nv_bfloat162*)&g_Clo[(size_t)row * D_ + col] = __halves2bfloat162(l0, l1);
            split2(acc[mt][nt][2], h0, l0); split2(acc[mt][nt][3], h1, l1);
            *(__nv_bfloat162*)&g_Chi[(size_t)(row + 8) * D_ + col] = __halves2bfloat162(h0, h1);
            *(__nv_bfloat162*)&g_Clo[(size_t)(row + 8) * D_ + col] = __halves2bfloat162(l0, l1);
        }
}

// ---------------------------------------------------------------------------
// K5: out[b][m][e] = sum_v context[m][v] * wo[e][v] on tensor cores.
// wo exact in bf16 -> 2 products: Ch*Wo + Cl*Wo.  BM=128, BN=128, BK=32.
// ---------------------------------------------------------------------------
__global__ __launch_bounds__(256) void out_mma_kernel(float* __restrict__ Out)
{
    __shared__ __nv_bfloat16 Ch[128][40];
    __shared__ __nv_bfloat16 Cl[128][40];
    __shared__ __nv_bfloat16 Ws[128][40];

    const int m0 = blockIdx.x * 128;
    const int e0 = blockIdx.y * 128;
    const int b  = blockIdx.z;
    const int tid  = threadIdx.x;
    const int warp = tid >> 5, lane = tid & 31;
    const int wm = warp >> 1, wn = warp & 1;
    const int lr = lane >> 2, lc = (lane & 3) * 2;

    const size_t cbase = ((size_t)b * N_ + m0) * D_;

    float acc[2][8][4];
    #pragma unroll
    for (int i = 0; i < 2; i++)
        #pragma unroll
        for (int j = 0; j < 8; j++)
            #pragma unroll
            for (int q = 0; q < 4; q++) acc[i][j][q] = 0.f;

    uint2 chv[4], clv[4], wov[4];
    #pragma unroll
    for (int t = 0; t < 4; t++) {
        int idx = t * 256 + tid;
        int r = idx >> 3, c = idx & 7;
        chv[t] = *(const uint2*)&g_Chi[cbase + (size_t)r * D_ + c * 4];
        clv[t] = *(const uint2*)&g_Clo[cbase + (size_t)r * D_ + c * 4];
        wov[t] = *(const uint2*)&g_Wob[(size_t)(e0 + r) * D_ + c * 4];
    }

    for (int k0 = 0; k0 < D_; k0 += 32) {
        #pragma unroll
        for (int t = 0; t < 4; t++) {
            int idx = t * 256 + tid;
            int r = idx >> 3, c = idx & 7;
            *(uint2*)&Ch[r][c * 4] = chv[t];
            *(uint2*)&Cl[r][c * 4] = clv[t];
            *(uint2*)&Ws[r][c * 4] = wov[t];
        }
        __syncthreads();

        if (k0 + 32 < D_) {
            int kn = k0 + 32;
            #pragma unroll
            for (int t = 0; t < 4; t++) {
                int idx = t * 256 + tid;
                int r = idx >> 3, c = idx & 7;
                chv[t] = *(const uint2*)&g_Chi[cbase + (size_t)r * D_ + kn + c * 4];
                clv[t] = *(const uint2*)&g_Clo[cbase + (size_t)r * D_ + kn + c * 4];
                wov[t] = *(const uint2*)&g_Wob[(size_t)(e0 + r) * D_ + kn + c * 4];
            }
        }

        #pragma unroll
        for (int ks = 0; ks < 32; ks += 16) {
            unsigned bw[8][2];
            #pragma unroll
            for (int np = 0; np < 4; np++) {
                int nrow = wn * 64 + np * 16 + ((lane >> 4) << 3) + (lane & 7);
                int ncol = ks + (((lane >> 3) & 1) << 3);
                unsigned t4[4];
                ldmx4(t4, &Ws[nrow][ncol]);
                bw[np*2][0] = t4[0]; bw[np*2][1] = t4[1];
                bw[np*2+1][0] = t4[2]; bw[np*2+1][1] = t4[3];
            }
            #pragma unroll
            for (int mt = 0; mt < 2; mt++) {
                int r0 = wm * 32 + mt * 16;
                unsigned ah[4], al[4];
                ldmx4(ah, &Ch[r0 + (lane & 15)][ks + ((lane >> 4) << 3)]);
                ldmx4(al, &Cl[r0 + (lane & 15)][ks + ((lane >> 4) << 3)]);
                #pragma unroll
                for (int nt = 0; nt < 8; nt++) mma16816(acc[mt][nt], ah, bw[nt]);
                #pragma unroll
                for (int nt = 0; nt < 8; nt++) mma16816(acc[mt][nt], al, bw[nt]);
            }
        }
        __syncthreads();
    }

    #pragma unroll
    for (int mt = 0; mt < 2; mt++)
        #pragma unroll
        for (int nt = 0; nt < 8; nt++) {
            int row = m0 + wm * 32 + mt * 16 + lr;
            int col = e0 + wn * 64 + nt * 8 + lc;
            *(float2*)&Out[((size_t)b * N_ + row) * E_ + col] =
                make_float2(acc[mt][nt][0], acc[mt][nt][1]);
            *(float2*)&Out[((size_t)b * N_ + row + 8) * E_ + col] =
                make_float2(acc[mt][nt][2], acc[mt][nt][3]);
        }
}

// ---------------------------------------------------------------------------
extern "C" void kernel_launch(void* const* d_in, const int* in_sizes, int n_in,
                              void* d_out, int out_size)
{
    const float* x  = (const float*)d_in[0];
    const float* wq = (const float*)d_in[1];
    const float* wk = (const float*)d_in[2];
    const float* wv = (const float*)d_in[3];
    const float* wo = (const float*)d_in[4];
    float* out = (float*)d_out;

    wconv_kernel  <<<192 * 1024 / 4 / 256, 256>>>(wq, wk, wv);
    woconv_kernel <<<E_ * D_ / 4 / 256, 256>>>(wo);
    qkv_mma_kernel<<<M_ / 64, 256>>>(x);
    energy_kernel <<<dim3(SPLITS, B_), 256>>>();
    ereduce_kernel<<<dim3(16, B_), 256>>>();
    context_kernel<<<M_ / 128, 256>>>();
    out_mma_kernel<<<dim3(N_ / 128, E_ / 128, B_), 256>>>(out);
}

// round 15
// speedup vs baseline: 1.1557x; 1.1557x over previous
#include <cuda_runtime.h>
#include <cuda_bf16.h>
#include <cuda_fp16.h>
#include <cstdint>

#define B_ 4
#define N_ 8192
#define E_ 1024
#define D_ 64
#define M_ (B_*N_)          // 32768 rows of X
#define SPLITS 64
#define ROWS_PER_SPLIT (N_/SPLITS)   // 128
#define SCALE_ 0.21650635094610965f  // sqrt(3/64)

using u64 = unsigned long long;

// Scratch (device globals; no allocation allowed)
__device__ float g_K[M_*D_];
__device__ float g_V[M_*D_];
__device__ float g_epart[B_*SPLITS*D_*D_];
__device__ __nv_bfloat16 g_Qhi[M_*D_];
__device__ __nv_bfloat16 g_Qlo[M_*D_];
__device__ __nv_bfloat16 g_eThi[B_*D_*D_];    // [b][v][k] = scale*energy[k][v]
__device__ __nv_bfloat16 g_eTlo[B_*D_*D_];
__device__ __nv_bfloat16 g_Chi[M_*D_];        // context hi/lo
__device__ __nv_bfloat16 g_Clo[M_*D_];
__device__ __half g_Wh[192*E_];               // [n][k] fp16 (exact +-2^-5)
__device__ __nv_bfloat16 g_Wob[E_*D_];        // [e][v], exact bf16

// ---------------------------------------------------------------------------
// helpers
// ---------------------------------------------------------------------------
__device__ __forceinline__ void split2(float x, __nv_bfloat16& h, __nv_bfloat16& l) {
    h = __float2bfloat16_rn(x);
    l = __float2bfloat16_rn(x - __bfloat162float(h));
}

// packed f32x2 (sm_100+): two IEEE fp32 FMAs per instruction
__device__ __forceinline__ u64 pack2(float lo, float hi) {
    u64 r; asm("mov.b64 %0, {%1, %2};" : "=l"(r) : "f"(lo), "f"(hi)); return r;
}
__device__ __forceinline__ void unpack2(u64 v, float& lo, float& hi) {
    asm("mov.b64 {%0, %1}, %2;" : "=f"(lo), "=f"(hi) : "l"(v));
}
__device__ __forceinline__ u64 ffma2(u64 a, u64 b, u64 c) {
    u64 d; asm("fma.rn.f32x2 %0, %1, %2, %3;" : "=l"(d) : "l"(a), "l"(b), "l"(c)); return d;
}

// D(16x8,f32) += A(16x16,bf16,row) * B(16x8,bf16,col)
__device__ __forceinline__ void mma16816(float* d, const unsigned* a, const unsigned* b) {
    asm volatile(
        "mma.sync.aligned.m16n8k16.row.col.f32.bf16.bf16.f32 "
        "{%0,%1,%2,%3}, {%4,%5,%6,%7}, {%8,%9}, {%0,%1,%2,%3};\n"
        : "+f"(d[0]), "+f"(d[1]), "+f"(d[2]), "+f"(d[3])
        : "r"(a[0]), "r"(a[1]), "r"(a[2]), "r"(a[3]), "r"(b[0]), "r"(b[1]));
}

// D(16x8,f32) += A(16x16,f16,row) * B(16x8,f16,col)
__device__ __forceinline__ void mma16816h(float* d, const unsigned* a, const unsigned* b) {
    asm volatile(
        "mma.sync.aligned.m16n8k16.row.col.f32.f16.f16.f32 "
        "{%0,%1,%2,%3}, {%4,%5,%6,%7}, {%8,%9}, {%0,%1,%2,%3};\n"
        : "+f"(d[0]), "+f"(d[1]), "+f"(d[2]), "+f"(d[3])
        : "r"(a[0]), "r"(a[1]), "r"(a[2]), "r"(a[3]), "r"(b[0]), "r"(b[1]));
}

__device__ __forceinline__ void ldmx4(unsigned* r, const void* p) {
    unsigned a = (unsigned)__cvta_generic_to_shared(p);
    asm volatile("ldmatrix.sync.aligned.m8n8.x4.shared.b16 {%0,%1,%2,%3}, [%4];"
        : "=r"(r[0]), "=r"(r[1]), "=r"(r[2]), "=r"(r[3]) : "r"(a));
}

// ---------------------------------------------------------------------------
// K0a: pre-convert qkv weights to fp16 (exact: +-2^-5), layout [n][k].
// ---------------------------------------------------------------------------
__global__ __launch_bounds__(256) void wconv_kernel(
    const float* __restrict__ Wq, const float* __restrict__ Wk, const float* __restrict__ Wv)
{
    int i = blockIdx.x * 256 + threadIdx.x;
    int n = i >> 8;
    int g = i & 255;
    const float* W = (n < 64) ? Wq : (n < 128 ? Wk : Wv);
    int rr = n & 63;
    float4 v = *(const float4*)&W[(size_t)rr * E_ + g * 4];
    __half2 p01 = __floats2half2_rn(v.x, v.y);
    __half2 p23 = __floats2half2_rn(v.z, v.w);
    uint2 u; u.x = *(unsigned*)&p01; u.y = *(unsigned*)&p23;
    *(uint2*)&g_Wh[(size_t)n * E_ + g * 4] = u;
}

// K0b: pre-convert wo to bf16 (exact: +-2^-3).  [E][64] row-major.
__global__ __launch_bounds__(256) void woconv_kernel(const float* __restrict__ Wo)
{
    int i = blockIdx.x * 256 + threadIdx.x;
    int r = i >> 4, g = i & 15;
    float4 v = *(const float4*)&Wo[(size_t)r * D_ + g * 4];
    __nv_bfloat162 p01 = __halves2bfloat162(__float2bfloat16_rn(v.x), __float2bfloat16_rn(v.y));
    __nv_bfloat162 p23 = __halves2bfloat162(__float2bfloat16_rn(v.z), __float2bfloat16_rn(v.w));
    uint2 u; u.x = *(unsigned*)&p01; u.y = *(unsigned*)&p23;
    *(uint2*)&g_Wob[(size_t)r * D_ + g * 4] = u;
}

// ---------------------------------------------------------------------------
// K1: fused QKV projection on fp16 MMA — SINGLE product (fp16 X has 11-bit
// mantissa; weights exact in fp16).  Halves tensor slots vs bf16 hi/lo.
// BM=64, BN=192, BK=32, 8 warps (2m x 4n), warp tile 32m x 48n.
// Q written as bf16 hi/lo from fp32 accum; K,V fp32 — downstream unchanged.
// ---------------------------------------------------------------------------
__global__ __launch_bounds__(256) void qkv_mma_kernel(const float* __restrict__ X)
{
    __shared__ __half Xs[64][40];    // 80B row stride: ldmatrix conflict-free
    __shared__ __half Wb[192][40];

    const int m0   = blockIdx.x * 64;
    const int tid  = threadIdx.x;
    const int warp = tid >> 5, lane = tid & 31;
    const int wm = warp >> 2, wn = warp & 3;
    const int lr = lane >> 2, lc = (lane & 3) * 2;

    float acc[2][6][4];
    #pragma unroll
    for (int i = 0; i < 2; i++)
        #pragma unroll
        for (int j = 0; j < 6; j++)
            #pragma unroll
            for (int q = 0; q < 4; q++) acc[i][j][q] = 0.f;

    // prefetch chunk 0: X 64x32 fp32 = 512 float4 (2/thr); W 192x32 f16 = 384 uint4
    float4 xv[2];
    uint4  wvb[3];
    #pragma unroll
    for (int t = 0; t < 2; t++) {
        int idx = t * 256 + tid;
        int r = idx >> 3, c = idx & 7;
        xv[t] = *(const float4*)&X[(size_t)(m0 + r) * E_ + c * 4];
    }
    #pragma unroll
    for (int t = 0; t < 3; t++) {
        int idx = t * 256 + tid;
        int r = idx >> 2, q = idx & 3;
        wvb[t] = *(const uint4*)&g_Wh[(size_t)r * E_ + q * 8];
    }

    for (int k0 = 0; k0 < E_; k0 += 32) {
        #pragma unroll
        for (int t = 0; t < 2; t++) {
            int idx = t * 256 + tid;
            int r = idx >> 3, c = idx & 7;
            __half2 p01 = __floats2half2_rn(xv[t].x, xv[t].y);
            __half2 p23 = __floats2half2_rn(xv[t].z, xv[t].w);
            uint2 u; u.x = *(unsigned*)&p01; u.y = *(unsigned*)&p23;
            *(uint2*)&Xs[r][c * 4] = u;
        }
        #pragma unroll
        for (int t = 0; t < 3; t++) {
            int idx = t * 256 + tid;
            int r = idx >> 2, q = idx & 3;
            *(uint4*)&Wb[r][q * 8] = wvb[t];
        }
        __syncthreads();

        if (k0 + 32 < E_) {
            int kn = k0 + 32;
            #pragma unroll
            for (int t = 0; t < 2; t++) {
                int idx = t * 256 + tid;
                int r = idx >> 3, c = idx & 7;
                xv[t] = *(const float4*)&X[(size_t)(m0 + r) * E_ + kn + c * 4];
            }
            #pragma unroll
            for (int t = 0; t < 3; t++) {
                int idx = t * 256 + tid;
                int r = idx >> 2, q = idx & 3;
                wvb[t] = *(const uint4*)&g_Wh[(size_t)r * E_ + kn + q * 8];
            }
        }

        #pragma unroll
        for (int ks = 0; ks < 32; ks += 16) {
            unsigned bf[6][2];
            #pragma unroll
            for (int np = 0; np < 3; np++) {
                int n0 = wn * 48 + np * 16;
                const __half* p =
                    &Wb[n0 + ((lane >> 4) << 3) + (lane & 7)][ks + (((lane >> 3) & 1) << 3)];
                unsigned t4[4];
                ldmx4(t4, p);
                bf[np*2][0] = t4[0]; bf[np*2][1] = t4[1];
                bf[np*2+1][0] = t4[2]; bf[np*2+1][1] = t4[3];
            }
            #pragma unroll
            for (int mt = 0; mt < 2; mt++) {
                int r0 = wm * 32 + mt * 16;
                unsigned ax[4];
                ldmx4(ax, &Xs[r0 + (lane & 15)][ks + ((lane >> 4) << 3)]);
                #pragma unroll
                for (int nt = 0; nt < 6; nt++) mma16816h(acc[mt][nt], ax, bf[nt]);
            }
        }
        __syncthreads();
    }

    // Epilogue: fragment n-range selects Q / K / V (8 | 64, never crosses)
    #pragma unroll
    for (int mt = 0; mt < 2; mt++)
        #pragma unroll
        for (int nt = 0; nt < 6; nt++) {
            int ng  = wn * 48 + nt * 8;
            int sel = ng >> 6;
            int col = (ng & 63) + lc;
            int row = m0 + wm * 32 + mt * 16 + lr;
            if (sel == 0) {
                __nv_bfloat16 h0,l0,h1,l1;
                split2(acc[mt][nt][0], h0, l0); split2(acc[mt][nt][1], h1, l1);
                *(__nv_bfloat162*)&g_Qhi[(size_t)row * D_ + col] = __halves2bfloat162(h0, h1);
                *(__nv_bfloat162*)&g_Qlo[(size_t)row * D_ + col] = __halves2bfloat162(l0, l1);
                split2(acc[mt][nt][2], h0, l0); split2(acc[mt][nt][3], h1, l1);
                *(__nv_bfloat162*)&g_Qhi[(size_t)(row + 8) * D_ + col] = __halves2bfloat162(h0, h1);
                *(__nv_bfloat162*)&g_Qlo[(size_t)(row + 8) * D_ + col] = __halves2bfloat162(l0, l1);
            } else {
                float* Out = (sel == 1) ? g_K : g_V;
                *(float2*)&Out[(size_t)row * D_ + col] =
                    make_float2(acc[mt][nt][0], acc[mt][nt][1]);
                *(float2*)&Out[(size_t)(row + 8) * D_ + col] =
                    make_float2(acc[mt][nt][2], acc[mt][nt][3]);
            }
        }
}

// ---------------------------------------------------------------------------
// K2: energy partials, fp32 SIMT with packed FFMA2 + 32-row tiles.
// ---------------------------------------------------------------------------
__global__ __launch_bounds__(256) void energy_kernel()
{
    const int s = blockIdx.x;
    const int b = blockIdx.y;
    const float* Kb = g_K + (size_t)b * N_ * D_;
    const float* Vb = g_V + (size_t)b * N_ * D_;
    const int n_base = s * ROWS_PER_SPLIT;

    __shared__ float Ks[32][D_];
    __shared__ float Vs[32][D_];

    const int tid = threadIdx.x;
    const int ty  = tid >> 4;
    const int tx  = tid & 15;

    u64 acc[4][2];
    #pragma unroll
    for (int i = 0; i < 4; i++) { acc[i][0] = 0ull; acc[i][1] = 0ull; }

    for (int c = 0; c < ROWS_PER_SPLIT; c += 32) {
        #pragma unroll
        for (int t = 0; t < 2; t++) {
            int idx = t * 256 + tid;
            int r  = idx >> 4;
            int c4 = idx & 15;
            *(float4*)&Ks[r][c4 * 4] = *(const float4*)&Kb[(size_t)(n_base + c + r) * D_ + c4 * 4];
            *(float4*)&Vs[r][c4 * 4] = *(const float4*)&Vb[(size_t)(n_base + c + r) * D_ + c4 * 4];
        }
        __syncthreads();
        #pragma unroll
        for (int n = 0; n < 32; n++) {
            float4 kv = *(const float4*)&Ks[n][ty * 4];
            ulonglong2 vv = *(const ulonglong2*)&Vs[n][tx * 4];
            u64 kd[4] = { pack2(kv.x, kv.x), pack2(kv.y, kv.y),
                          pack2(kv.z, kv.z), pack2(kv.w, kv.w) };
            #pragma unroll
            for (int i = 0; i < 4; i++) {
                acc[i][0] = ffma2(kd[i], vv.x, acc[i][0]);
                acc[i][1] = ffma2(kd[i], vv.y, acc[i][1]);
            }
        }
        __syncthreads();
    }

    float* ep = g_epart + ((size_t)(b * SPLITS + s)) * (D_ * D_);
    #pragma unroll
    for (int i = 0; i < 4; i++) {
        float e0, e1, e2, e3;
        unpack2(acc[i][0], e0, e1);
        unpack2(acc[i][1], e2, e3);
        *(float4*)&ep[(ty * 4 + i) * D_ + tx * 4] = make_float4(e0, e1, e2, e3);
    }
}

// ---------------------------------------------------------------------------
// K3: reduce epart over 64 splits -> scaled eT[v][k] as bf16 hi/lo.
// ---------------------------------------------------------------------------
__global__ __launch_bounds__(256) void ereduce_kernel()
{
    const int b = blockIdx.y;
    const int base = blockIdx.x * 256 + threadIdx.x;   // 0..4095 = k*64+v
    const float* ep = g_epart + (size_t)b * SPLITS * D_ * D_ + base;
    float s = 0.f;
    #pragma unroll
    for (int sp = 0; sp < SPLITS; sp++)
        s += ep[(size_t)sp * (D_ * D_)];
    s *= SCALE_;
    int k = base >> 6;
    int v = base & 63;
    __nv_bfloat16 h, l;
    split2(s, h, l);
    g_eThi[(size_t)b * D_ * D_ + v * D_ + k] = h;
    g_eTlo[(size_t)b * D_ * D_ + v * D_ + k] = l;
}

// ---------------------------------------------------------------------------
// K4: context[m][v] = sum_k Q[m][k] * (scale*energy)[k][v] on tensor cores.
// 3-product split: Qh*Eh + Qh*El + Ql*Eh.  BM=128, BN=64, BK=32.
// ---------------------------------------------------------------------------
__global__ __launch_bounds__(256) void context_kernel()
{
    __shared__ __nv_bfloat16 Qh[128][40];
    __shared__ __nv_bfloat16 Ql[128][40];
    __shared__ __nv_bfloat16 Eh[64][40];
    __shared__ __nv_bfloat16 El[64][40];

    const int m0 = blockIdx.x * 128;
    const int b  = m0 >> 13;
    const size_t eb = (size_t)b * D_ * D_;
    const int tid  = threadIdx.x;
    const int warp = tid >> 5, lane = tid & 31;
    const int wm = warp >> 1, wn = warp & 1;
    const int lr = lane >> 2, lc = (lane & 3) * 2;

    float acc[2][4][4];
    #pragma unroll
    for (int i = 0; i < 2; i++)
        #pragma unroll
        for (int j = 0; j < 4; j++)
            #pragma unroll
            for (int q = 0; q < 4; q++) acc[i][j][q] = 0.f;

    for (int k0 = 0; k0 < D_; k0 += 32) {
        #pragma unroll
        for (int t = 0; t < 4; t++) {
            int idx = t * 256 + tid;
            int r = idx >> 3, c = idx & 7;
            *(uint2*)&Qh[r][c * 4] = *(const uint2*)&g_Qhi[(size_t)(m0 + r) * D_ + k0 + c * 4];
            *(uint2*)&Ql[r][c * 4] = *(const uint2*)&g_Qlo[(size_t)(m0 + r) * D_ + k0 + c * 4];
        }
        #pragma unroll
        for (int t = 0; t < 2; t++) {
            int idx = t * 256 + tid;
            int r = idx >> 3, c = idx & 7;
            *(uint2*)&Eh[r][c * 4] = *(const uint2*)&g_eThi[eb + (size_t)r * D_ + k0 + c * 4];
            *(uint2*)&El[r][c * 4] = *(const uint2*)&g_eTlo[eb + (size_t)r * D_ + k0 + c * 4];
        }
        __syncthreads();

        #pragma unroll
        for (int ks = 0; ks < 32; ks += 16) {
            unsigned bh[4][2], bl[4][2];
            #pragma unroll
            for (int np = 0; np < 2; np++) {
                int nrow = wn * 32 + np * 16 + ((lane >> 4) << 3) + (lane & 7);
                int ncol = ks + (((lane >> 3) & 1) << 3);
                unsigned t4[4];
                ldmx4(t4, &Eh[nrow][ncol]);
                bh[np*2][0] = t4[0]; bh[np*2][1] = t4[1];
                bh[np*2+1][0] = t4[2]; bh[np*2+1][1] = t4[3];
                ldmx4(t4, &El[nrow][ncol]);
                bl[np*2][0] = t4[0]; bl[np*2][1] = t4[1];
                bl[np*2+1][0] = t4[2]; bl[np*2+1][1] = t4[3];
            }
            #pragma unroll
            for (int mt = 0; mt < 2; mt++) {
                int r0 = wm * 32 + mt * 16;
                unsigned ah[4], al[4];
                ldmx4(ah, &Qh[r0 + (lane & 15)][ks + ((lane >> 4) << 3)]);
                ldmx4(al, &Ql[r0 + (lane & 15)][ks + ((lane >> 4) << 3)]);
                #pragma unroll
                for (int nt = 0; nt < 4; nt++) mma16816(acc[mt][nt], ah, bh[nt]);
                #pragma unroll
                for (int nt = 0; nt < 4; nt++) mma16816(acc[mt][nt], ah, bl[nt]);
                #pragma unroll
                for (int nt = 0; nt < 4; nt++) mma16816(acc[mt][nt], al, bh[nt]);
            }
        }
        __syncthreads();
    }

    #pragma unroll
    for (int mt = 0; mt < 2; mt++)
        #pragma unroll
        for (int nt = 0; nt < 4; nt++) {
            int row = m0 + wm * 32 + mt * 16 + lr;
            int col = wn * 32 + nt * 8 + lc;
            __nv_bfloat16 h0,l0,h1,l1;
            split2(acc[mt][nt][0], h0, l0); split2(acc[mt][nt][1], h1, l1);
            *(__nv_bfloat162*)&g_Chi[(size_t)row * D_ + col] = __halves2bfloat162(h0, h1);
            *(__nv_bfloat162*)&g_Clo[(size_t)row * D_ + col] = __halves2bfloat162(l0, l1);
            split2(acc[mt][nt][2], h0, l0); split2(acc[mt][nt][3], h1, l1);
            *(__nv_bfloat162*)&g_Chi[(size_t)(row + 8) * D_ + col] = __halves2bfloat162(h0, h1);
            *(__nv_bfloat162*)&g_Clo[(size_t)(row + 8) * D_ + col] = __halves2bfloat162(l0, l1);
        }
}

// ---------------------------------------------------------------------------
// K5: out[b][m][e] = sum_v context[m][v] * wo[e][v] on tensor cores.
// wo exact in bf16 -> 2 products: Ch*Wo + Cl*Wo.  BM=128, BN=128, BK=32.
// ---------------------------------------------------------------------------
__global__ __launch_bounds__(256) void out_mma_kernel(float* __restrict__ Out)
{
    __shared__ __nv_bfloat16 Ch[128][40];
    __shared__ __nv_bfloat16 Cl[128][40];
    __shared__ __nv_bfloat16 Ws[128][40];

    const int m0 = blockIdx.x * 128;
    const int e0 = blockIdx.y * 128;
    const int b  = blockIdx.z;
    const int tid  = threadIdx.x;
    const int warp = tid >> 5, lane = tid & 31;
    const int wm = warp >> 1, wn = warp & 1;
    const int lr = lane >> 2, lc = (lane & 3) * 2;

    const size_t cbase = ((size_t)b * N_ + m0) * D_;

    float acc[2][8][4];
    #pragma unroll
    for (int i = 0; i < 2; i++)
        #pragma unroll
        for (int j = 0; j < 8; j++)
            #pragma unroll
            for (int q = 0; q < 4; q++) acc[i][j][q] = 0.f;

    uint2 chv[4], clv[4], wov[4];
    #pragma unroll
    for (int t = 0; t < 4; t++) {
        int idx = t * 256 + tid;
        int r = idx >> 3, c = idx & 7;
        chv[t] = *(const uint2*)&g_Chi[cbase + (size_t)r * D_ + c * 4];
        clv[t] = *(const uint2*)&g_Clo[cbase + (size_t)r * D_ + c * 4];
        wov[t] = *(const uint2*)&g_Wob[(size_t)(e0 + r) * D_ + c * 4];
    }

    for (int k0 = 0; k0 < D_; k0 += 32) {
        #pragma unroll
        for (int t = 0; t < 4; t++) {
            int idx = t * 256 + tid;
            int r = idx >> 3, c = idx & 7;
            *(uint2*)&Ch[r][c * 4] = chv[t];
            *(uint2*)&Cl[r][c * 4] = clv[t];
            *(uint2*)&Ws[r][c * 4] = wov[t];
        }
        __syncthreads();

        if (k0 + 32 < D_) {
            int kn = k0 + 32;
            #pragma unroll
            for (int t = 0; t < 4; t++) {
                int idx = t * 256 + tid;
                int r = idx >> 3, c = idx & 7;
                chv[t] = *(const uint2*)&g_Chi[cbase + (size_t)r * D_ + kn + c * 4];
                clv[t] = *(const uint2*)&g_Clo[cbase + (size_t)r * D_ + kn + c * 4];
                wov[t] = *(const uint2*)&g_Wob[(size_t)(e0 + r) * D_ + kn + c * 4];
            }
        }

        #pragma unroll
        for (int ks = 0; ks < 32; ks += 16) {
            unsigned bw[8][2];
            #pragma unroll
            for (int np = 0; np < 4; np++) {
                int nrow = wn * 64 + np * 16 + ((lane >> 4) << 3) + (lane & 7);
                int ncol = ks + (((lane >> 3) & 1) << 3);
                unsigned t4[4];
                ldmx4(t4, &Ws[nrow][ncol]);
                bw[np*2][0] = t4[0]; bw[np*2][1] = t4[1];
                bw[np*2+1][0] = t4[2]; bw[np*2+1][1] = t4[3];
            }
            #pragma unroll
            for (int mt = 0; mt < 2; mt++) {
                int r0 = wm * 32 + mt * 16;
                unsigned ah[4], al[4];
                ldmx4(ah, &Ch[r0 + (lane & 15)][ks + ((lane >> 4) << 3)]);
                ldmx4(al, &Cl[r0 + (lane & 15)][ks + ((lane >> 4) << 3)]);
                #pragma unroll
                for (int nt = 0; nt < 8; nt++) mma16816(acc[mt][nt], ah, bw[nt]);
                #pragma unroll
                for (int nt = 0; nt < 8; nt++) mma16816(acc[mt][nt], al, bw[nt]);
            }
        }
        __syncthreads();
    }

    #pragma unroll
    for (int mt = 0; mt < 2; mt++)
        #pragma unroll
        for (int nt = 0; nt < 8; nt++) {
            int row = m0 + wm * 32 + mt * 16 + lr;
            int col = e0 + wn * 64 + nt * 8 + lc;
            *(float2*)&Out[((size_t)b * N_ + row) * E_ + col] =
                make_float2(acc[mt][nt][0], acc[mt][nt][1]);
            *(float2*)&Out[((size_t)b * N_ + row + 8) * E_ + col] =
                make_float2(acc[mt][nt][2], acc[mt][nt][3]);
        }
}

// ---------------------------------------------------------------------------
extern "C" void kernel_launch(void* const* d_in, const int* in_sizes, int n_in,
                              void* d_out, int out_size)
{
    const float* x  = (const float*)d_in[0];
    const float* wq = (const float*)d_in[1];
    const float* wk = (const float*)d_in[2];
    const float* wv = (const float*)d_in[3];
    const float* wo = (const float*)d_in[4];
    float* out = (float*)d_out;

    wconv_kernel  <<<192 * 1024 / 4 / 256, 256>>>(wq, wk, wv);
    woconv_kernel <<<E_ * D_ / 4 / 256, 256>>>(wo);
    qkv_mma_kernel<<<M_ / 64, 256>>>(x);
    energy_kernel <<<dim3(SPLITS, B_), 256>>>();
    ereduce_kernel<<<dim3(16, B_), 256>>>();
    context_kernel<<<M_ / 128, 256>>>();
    out_mma_kernel<<<dim3(N_ / 128, E_ / 128, B_), 256>>>(out);
}

// round 16
// speedup vs baseline: 1.3555x; 1.1729x over previous
#include <cuda_runtime.h>
#include <cuda_bf16.h>
#include <cuda_fp16.h>
#include <cstdint>

#define B_ 4
#define N_ 8192
#define E_ 1024
#define D_ 64
#define M_ (B_*N_)          // 32768 rows of X
#define SPLITS 64
#define ROWS_PER_SPLIT (N_/SPLITS)   // 128
#define SCALE_ 0.21650635094610965f  // sqrt(3/64)

using u64 = unsigned long long;

// Scratch (device globals; no allocation allowed)
__device__ float g_K[M_*D_];
__device__ float g_V[M_*D_];
__device__ float g_epart[B_*SPLITS*D_*D_];
__device__ __half g_Q[M_*D_];                 // Q in fp16 (single-product path)
__device__ __half g_eT[B_*D_*D_];             // [b][v][k] = scale*energy[k][v], fp16
__device__ __half g_C[M_*D_];                 // context, fp16
__device__ __half g_Wh[192*E_];               // [n][k] fp16 (exact +-2^-5)
__device__ __half g_Woh[E_*D_];               // [e][v] fp16 (exact +-2^-3)

// ---------------------------------------------------------------------------
// helpers
// ---------------------------------------------------------------------------
// packed f32x2 (sm_100+): two IEEE fp32 FMAs per instruction
__device__ __forceinline__ u64 pack2(float lo, float hi) {
    u64 r; asm("mov.b64 %0, {%1, %2};" : "=l"(r) : "f"(lo), "f"(hi)); return r;
}
__device__ __forceinline__ void unpack2(u64 v, float& lo, float& hi) {
    asm("mov.b64 {%0, %1}, %2;" : "=f"(lo), "=f"(hi) : "l"(v));
}
__device__ __forceinline__ u64 ffma2(u64 a, u64 b, u64 c) {
    u64 d; asm("fma.rn.f32x2 %0, %1, %2, %3;" : "=l"(d) : "l"(a), "l"(b), "l"(c)); return d;
}

// D(16x8,f32) += A(16x16,f16,row) * B(16x8,f16,col)
__device__ __forceinline__ void mma16816h(float* d, const unsigned* a, const unsigned* b) {
    asm volatile(
        "mma.sync.aligned.m16n8k16.row.col.f32.f16.f16.f32 "
        "{%0,%1,%2,%3}, {%4,%5,%6,%7}, {%8,%9}, {%0,%1,%2,%3};\n"
        : "+f"(d[0]), "+f"(d[1]), "+f"(d[2]), "+f"(d[3])
        : "r"(a[0]), "r"(a[1]), "r"(a[2]), "r"(a[3]), "r"(b[0]), "r"(b[1]));
}

__device__ __forceinline__ void ldmx4(unsigned* r, const void* p) {
    unsigned a = (unsigned)__cvta_generic_to_shared(p);
    asm volatile("ldmatrix.sync.aligned.m8n8.x4.shared.b16 {%0,%1,%2,%3}, [%4];"
        : "=r"(r[0]), "=r"(r[1]), "=r"(r[2]), "=r"(r[3]) : "r"(a));
}

// ---------------------------------------------------------------------------
// K0a: pre-convert qkv weights to fp16 (exact: +-2^-5), layout [n][k].
// ---------------------------------------------------------------------------
__global__ __launch_bounds__(256) void wconv_kernel(
    const float* __restrict__ Wq, const float* __restrict__ Wk, const float* __restrict__ Wv)
{
    int i = blockIdx.x * 256 + threadIdx.x;
    int n = i >> 8;
    int g = i & 255;
    const float* W = (n < 64) ? Wq : (n < 128 ? Wk : Wv);
    int rr = n & 63;
    float4 v = *(const float4*)&W[(size_t)rr * E_ + g * 4];
    __half2 p01 = __floats2half2_rn(v.x, v.y);
    __half2 p23 = __floats2half2_rn(v.z, v.w);
    uint2 u; u.x = *(unsigned*)&p01; u.y = *(unsigned*)&p23;
    *(uint2*)&g_Wh[(size_t)n * E_ + g * 4] = u;
}

// K0b: pre-convert wo to fp16 (exact: +-2^-3).  [E][64] row-major.
__global__ __launch_bounds__(256) void woconv_kernel(const float* __restrict__ Wo)
{
    int i = blockIdx.x * 256 + threadIdx.x;
    int r = i >> 4, g = i & 15;
    float4 v = *(const float4*)&Wo[(size_t)r * D_ + g * 4];
    __half2 p01 = __floats2half2_rn(v.x, v.y);
    __half2 p23 = __floats2half2_rn(v.z, v.w);
    uint2 u; u.x = *(unsigned*)&p01; u.y = *(unsigned*)&p23;
    *(uint2*)&g_Woh[(size_t)r * D_ + g * 4] = u;
}

// ---------------------------------------------------------------------------
// K1: fused QKV projection on fp16 MMA, single product.
// BM=64, BN=192, BK=32, 8 warps (2m x 4n), warp tile 32m x 48n.
// Q written fp16; K,V fp32 for the fp32 energy path.
// ---------------------------------------------------------------------------
__global__ __launch_bounds__(256) void qkv_mma_kernel(const float* __restrict__ X)
{
    __shared__ __half Xs[64][40];    // 80B row stride: ldmatrix conflict-free
    __shared__ __half Wb[192][40];

    const int m0   = blockIdx.x * 64;
    const int tid  = threadIdx.x;
    const int warp = tid >> 5, lane = tid & 31;
    const int wm = warp >> 2, wn = warp & 3;
    const int lr = lane >> 2, lc = (lane & 3) * 2;

    float acc[2][6][4];
    #pragma unroll
    for (int i = 0; i < 2; i++)
        #pragma unroll
        for (int j = 0; j < 6; j++)
            #pragma unroll
            for (int q = 0; q < 4; q++) acc[i][j][q] = 0.f;

    float4 xv[2];
    uint4  wvb[3];
    #pragma unroll
    for (int t = 0; t < 2; t++) {
        int idx = t * 256 + tid;
        int r = idx >> 3, c = idx & 7;
        xv[t] = *(const float4*)&X[(size_t)(m0 + r) * E_ + c * 4];
    }
    #pragma unroll
    for (int t = 0; t < 3; t++) {
        int idx = t * 256 + tid;
        int r = idx >> 2, q = idx & 3;
        wvb[t] = *(const uint4*)&g_Wh[(size_t)r * E_ + q * 8];
    }

    for (int k0 = 0; k0 < E_; k0 += 32) {
        #pragma unroll
        for (int t = 0; t < 2; t++) {
            int idx = t * 256 + tid;
            int r = idx >> 3, c = idx & 7;
            __half2 p01 = __floats2half2_rn(xv[t].x, xv[t].y);
            __half2 p23 = __floats2half2_rn(xv[t].z, xv[t].w);
            uint2 u; u.x = *(unsigned*)&p01; u.y = *(unsigned*)&p23;
            *(uint2*)&Xs[r][c * 4] = u;
        }
        #pragma unroll
        for (int t = 0; t < 3; t++) {
            int idx = t * 256 + tid;
            int r = idx >> 2, q = idx & 3;
            *(uint4*)&Wb[r][q * 8] = wvb[t];
        }
        __syncthreads();

        if (k0 + 32 < E_) {
            int kn = k0 + 32;
            #pragma unroll
            for (int t = 0; t < 2; t++) {
                int idx = t * 256 + tid;
                int r = idx >> 3, c = idx & 7;
                xv[t] = *(const float4*)&X[(size_t)(m0 + r) * E_ + kn + c * 4];
            }
            #pragma unroll
            for (int t = 0; t < 3; t++) {
                int idx = t * 256 + tid;
                int r = idx >> 2, q = idx & 3;
                wvb[t] = *(const uint4*)&g_Wh[(size_t)r * E_ + kn + q * 8];
            }
        }

        #pragma unroll
        for (int ks = 0; ks < 32; ks += 16) {
            unsigned bf[6][2];
            #pragma unroll
            for (int np = 0; np < 3; np++) {
                int n0 = wn * 48 + np * 16;
                const __half* p =
                    &Wb[n0 + ((lane >> 4) << 3) + (lane & 7)][ks + (((lane >> 3) & 1) << 3)];
                unsigned t4[4];
                ldmx4(t4, p);
                bf[np*2][0] = t4[0]; bf[np*2][1] = t4[1];
                bf[np*2+1][0] = t4[2]; bf[np*2+1][1] = t4[3];
            }
            #pragma unroll
            for (int mt = 0; mt < 2; mt++) {
                int r0 = wm * 32 + mt * 16;
                unsigned ax[4];
                ldmx4(ax, &Xs[r0 + (lane & 15)][ks + ((lane >> 4) << 3)]);
                #pragma unroll
                for (int nt = 0; nt < 6; nt++) mma16816h(acc[mt][nt], ax, bf[nt]);
            }
        }
        __syncthreads();
    }

    // Epilogue: fragment n-range selects Q / K / V (8 | 64, never crosses)
    #pragma unroll
    for (int mt = 0; mt < 2; mt++)
        #pragma unroll
        for (int nt = 0; nt < 6; nt++) {
            int ng  = wn * 48 + nt * 8;
            int sel = ng >> 6;
            int col = (ng & 63) + lc;
            int row = m0 + wm * 32 + mt * 16 + lr;
            if (sel == 0) {
                __half2 p0 = __floats2half2_rn(acc[mt][nt][0], acc[mt][nt][1]);
                __half2 p1 = __floats2half2_rn(acc[mt][nt][2], acc[mt][nt][3]);
                *(__half2*)&g_Q[(size_t)row * D_ + col] = p0;
                *(__half2*)&g_Q[(size_t)(row + 8) * D_ + col] = p1;
            } else {
                float* Out = (sel == 1) ? g_K : g_V;
                *(float2*)&Out[(size_t)row * D_ + col] =
                    make_float2(acc[mt][nt][0], acc[mt][nt][1]);
                *(float2*)&Out[(size_t)(row + 8) * D_ + col] =
                    make_float2(acc[mt][nt][2], acc[mt][nt][3]);
            }
        }
}

// ---------------------------------------------------------------------------
// K2: energy partials, fp32 SIMT with packed FFMA2 + 32-row tiles.
// ---------------------------------------------------------------------------
__global__ __launch_bounds__(256) void energy_kernel()
{
    const int s = blockIdx.x;
    const int b = blockIdx.y;
    const float* Kb = g_K + (size_t)b * N_ * D_;
    const float* Vb = g_V + (size_t)b * N_ * D_;
    const int n_base = s * ROWS_PER_SPLIT;

    __shared__ float Ks[32][D_];
    __shared__ float Vs[32][D_];

    const int tid = threadIdx.x;
    const int ty  = tid >> 4;
    const int tx  = tid & 15;

    u64 acc[4][2];
    #pragma unroll
    for (int i = 0; i < 4; i++) { acc[i][0] = 0ull; acc[i][1] = 0ull; }

    for (int c = 0; c < ROWS_PER_SPLIT; c += 32) {
        #pragma unroll
        for (int t = 0; t < 2; t++) {
            int idx = t * 256 + tid;
            int r  = idx >> 4;
            int c4 = idx & 15;
            *(float4*)&Ks[r][c4 * 4] = *(const float4*)&Kb[(size_t)(n_base + c + r) * D_ + c4 * 4];
            *(float4*)&Vs[r][c4 * 4] = *(const float4*)&Vb[(size_t)(n_base + c + r) * D_ + c4 * 4];
        }
        __syncthreads();
        #pragma unroll
        for (int n = 0; n < 32; n++) {
            float4 kv = *(const float4*)&Ks[n][ty * 4];
            ulonglong2 vv = *(const ulonglong2*)&Vs[n][tx * 4];
            u64 kd[4] = { pack2(kv.x, kv.x), pack2(kv.y, kv.y),
                          pack2(kv.z, kv.z), pack2(kv.w, kv.w) };
            #pragma unroll
            for (int i = 0; i < 4; i++) {
                acc[i][0] = ffma2(kd[i], vv.x, acc[i][0]);
                acc[i][1] = ffma2(kd[i], vv.y, acc[i][1]);
            }
        }
        __syncthreads();
    }

    float* ep = g_epart + ((size_t)(b * SPLITS + s)) * (D_ * D_);
    #pragma unroll
    for (int i = 0; i < 4; i++) {
        float e0, e1, e2, e3;
        unpack2(acc[i][0], e0, e1);
        unpack2(acc[i][1], e2, e3);
        *(float4*)&ep[(ty * 4 + i) * D_ + tx * 4] = make_float4(e0, e1, e2, e3);
    }
}

// ---------------------------------------------------------------------------
// K3: reduce epart over 64 splits -> scaled eT[v][k] in fp16.
// ---------------------------------------------------------------------------
__global__ __launch_bounds__(256) void ereduce_kernel()
{
    const int b = blockIdx.y;
    const int base = blockIdx.x * 256 + threadIdx.x;   // 0..4095 = k*64+v
    const float* ep = g_epart + (size_t)b * SPLITS * D_ * D_ + base;
    float s = 0.f;
    #pragma unroll
    for (int sp = 0; sp < SPLITS; sp++)
        s += ep[(size_t)sp * (D_ * D_)];
    s *= SCALE_;
    int k = base >> 6;
    int v = base & 63;
    g_eT[(size_t)b * D_ * D_ + v * D_ + k] = __float2half_rn(s);
}

// ---------------------------------------------------------------------------
// K4: context[m][v] = sum_k Q[m][k] * (scale*energy)[k][v], fp16 single product.
// BM=128, BN=64, BK=32.  8 warps (4m x 2n).  Writes context fp16.
// ---------------------------------------------------------------------------
__global__ __launch_bounds__(256) void context_kernel()
{
    __shared__ __half Qs[128][40];
    __shared__ __half Es[64][40];

    const int m0 = blockIdx.x * 128;
    const int b  = m0 >> 13;
    const size_t eb = (size_t)b * D_ * D_;
    const int tid  = threadIdx.x;
    const int warp = tid >> 5, lane = tid & 31;
    const int wm = warp >> 1, wn = warp & 1;
    const int lr = lane >> 2, lc = (lane & 3) * 2;

    float acc[2][4][4];
    #pragma unroll
    for (int i = 0; i < 2; i++)
        #pragma unroll
        for (int j = 0; j < 4; j++)
            #pragma unroll
            for (int q = 0; q < 4; q++) acc[i][j][q] = 0.f;

    for (int k0 = 0; k0 < D_; k0 += 32) {
        #pragma unroll
        for (int t = 0; t < 4; t++) {
            int idx = t * 256 + tid;
            int r = idx >> 3, c = idx & 7;
            *(uint2*)&Qs[r][c * 4] = *(const uint2*)&g_Q[(size_t)(m0 + r) * D_ + k0 + c * 4];
        }
        #pragma unroll
        for (int t = 0; t < 2; t++) {
            int idx = t * 256 + tid;
            int r = idx >> 3, c = idx & 7;
            *(uint2*)&Es[r][c * 4] = *(const uint2*)&g_eT[eb + (size_t)r * D_ + k0 + c * 4];
        }
        __syncthreads();

        #pragma unroll
        for (int ks = 0; ks < 32; ks += 16) {
            unsigned be[4][2];
            #pragma unroll
            for (int np = 0; np < 2; np++) {
                int nrow = wn * 32 + np * 16 + ((lane >> 4) << 3) + (lane & 7);
                int ncol = ks + (((lane >> 3) & 1) << 3);
                unsigned t4[4];
                ldmx4(t4, &Es[nrow][ncol]);
                be[np*2][0] = t4[0]; be[np*2][1] = t4[1];
                be[np*2+1][0] = t4[2]; be[np*2+1][1] = t4[3];
            }
            #pragma unroll
            for (int mt = 0; mt < 2; mt++) {
                int r0 = wm * 32 + mt * 16;
                unsigned aq[4];
                ldmx4(aq, &Qs[r0 + (lane & 15)][ks + ((lane >> 4) << 3)]);
                #pragma unroll
                for (int nt = 0; nt < 4; nt++) mma16816h(acc[mt][nt], aq, be[nt]);
            }
        }
        __syncthreads();
    }

    #pragma unroll
    for (int mt = 0; mt < 2; mt++)
        #pragma unroll
        for (int nt = 0; nt < 4; nt++) {
            int row = m0 + wm * 32 + mt * 16 + lr;
            int col = wn * 32 + nt * 8 + lc;
            __half2 p0 = __floats2half2_rn(acc[mt][nt][0], acc[mt][nt][1]);
            __half2 p1 = __floats2half2_rn(acc[mt][nt][2], acc[mt][nt][3]);
            *(__half2*)&g_C[(size_t)row * D_ + col] = p0;
            *(__half2*)&g_C[(size_t)(row + 8) * D_ + col] = p1;
        }
}

// ---------------------------------------------------------------------------
// K5: out[b][m][e] = sum_v context[m][v] * wo[e][v], fp16 single product
// (wo exact in fp16).  BM=128, BN=128, BK=32, 8 warps (4m x 2n), 32m x 64n.
// ---------------------------------------------------------------------------
__global__ __launch_bounds__(256) void out_mma_kernel(float* __restrict__ Out)
{
    __shared__ __half Cs[128][40];
    __shared__ __half Ws[128][40];

    const int m0 = blockIdx.x * 128;
    const int e0 = blockIdx.y * 128;
    const int b  = blockIdx.z;
    const int tid  = threadIdx.x;
    const int warp = tid >> 5, lane = tid & 31;
    const int wm = warp >> 1, wn = warp & 1;
    const int lr = lane >> 2, lc = (lane & 3) * 2;

    const size_t cbase = ((size_t)b * N_ + m0) * D_;

    float acc[2][8][4];
    #pragma unroll
    for (int i = 0; i < 2; i++)
        #pragma unroll
        for (int j = 0; j < 8; j++)
            #pragma unroll
            for (int q = 0; q < 4; q++) acc[i][j][q] = 0.f;

    uint2 cv[4], wv[4];
    #pragma unroll
    for (int t = 0; t < 4; t++) {
        int idx = t * 256 + tid;
        int r = idx >> 3, c = idx & 7;
        cv[t] = *(const uint2*)&g_C[cbase + (size_t)r * D_ + c * 4];
        wv[t] = *(const uint2*)&g_Woh[(size_t)(e0 + r) * D_ + c * 4];
    }

    for (int k0 = 0; k0 < D_; k0 += 32) {
        #pragma unroll
        for (int t = 0; t < 4; t++) {
            int idx = t * 256 + tid;
            int r = idx >> 3, c = idx & 7;
            *(uint2*)&Cs[r][c * 4] = cv[t];
            *(uint2*)&Ws[r][c * 4] = wv[t];
        }
        __syncthreads();

        if (k0 + 32 < D_) {
            int kn = k0 + 32;
            #pragma unroll
            for (int t = 0; t < 4; t++) {
                int idx = t * 256 + tid;
                int r = idx >> 3, c = idx & 7;
                cv[t] = *(const uint2*)&g_C[cbase + (size_t)r * D_ + kn + c * 4];
                wv[t] = *(const uint2*)&g_Woh[(size_t)(e0 + r) * D_ + kn + c * 4];
            }
        }

        #pragma unroll
        for (int ks = 0; ks < 32; ks += 16) {
            unsigned bw[8][2];
            #pragma unroll
            for (int np = 0; np < 4; np++) {
                int nrow = wn * 64 + np * 16 + ((lane >> 4) << 3) + (lane & 7);
                int ncol = ks + (((lane >> 3) & 1) << 3);
                unsigned t4[4];
                ldmx4(t4, &Ws[nrow][ncol]);
                bw[np*2][0] = t4[0]; bw[np*2][1] = t4[1];
                bw[np*2+1][0] = t4[2]; bw[np*2+1][1] = t4[3];
            }
            #pragma unroll
            for (int mt = 0; mt < 2; mt++) {
                int r0 = wm * 32 + mt * 16;
                unsigned ac[4];
                ldmx4(ac, &Cs[r0 + (lane & 15)][ks + ((lane >> 4) << 3)]);
                #pragma unroll
                for (int nt = 0; nt < 8; nt++) mma16816h(acc[mt][nt], ac, bw[nt]);
            }
        }
        __syncthreads();
    }

    #pragma unroll
    for (int mt = 0; mt < 2; mt++)
        #pragma unroll
        for (int nt = 0; nt < 8; nt++) {
            int row = m0 + wm * 32 + mt * 16 + lr;
            int col = e0 + wn * 64 + nt * 8 + lc;
            *(float2*)&Out[((size_t)b * N_ + row) * E_ + col] =
                make_float2(acc[mt][nt][0], acc[mt][nt][1]);
            *(float2*)&Out[((size_t)b * N_ + row + 8) * E_ + col] =
                make_float2(acc[mt][nt][2], acc[mt][nt][3]);
        }
}

// ---------------------------------------------------------------------------
extern "C" void kernel_launch(void* const* d_in, const int* in_sizes, int n_in,
                              void* d_out, int out_size)
{
    const float* x  = (const float*)d_in[0];
    const float* wq = (const float*)d_in[1];
    const float* wk = (const float*)d_in[2];
    const float* wv = (const float*)d_in[3];
    const float* wo = (const float*)d_in[4];
    float* out = (float*)d_out;

    wconv_kernel  <<<192 * 1024 / 4 / 256, 256>>>(wq, wk, wv);
    woconv_kernel <<<E_ * D_ / 4 / 256, 256>>>(wo);
    qkv_mma_kernel<<<M_ / 64, 256>>>(x);
    energy_kernel <<<dim3(SPLITS, B_), 256>>>();
    ereduce_kernel<<<dim3(16, B_), 256>>>();
    context_kernel<<<M_ / 128, 256>>>();
    out_mma_kernel<<<dim3(N_ / 128, E_ / 128, B_), 256>>>(out);
}

// round 17
// speedup vs baseline: 1.3746x; 1.0141x over previous
#include <cuda_runtime.h>
#include <cuda_bf16.h>
#include <cuda_fp16.h>
#include <cstdint>

#define B_ 4
#define N_ 8192
#define E_ 1024
#define D_ 64
#define M_ (B_*N_)          // 32768 rows of X
#define SPLITS 64
#define ROWS_PER_SPLIT (N_/SPLITS)   // 128
#define SCALE_ 0.21650635094610965f  // sqrt(3/64)

// Scratch (device globals; no allocation allowed)
__device__ __half g_KT[B_*D_*N_];             // [b][d][n]  K transposed, fp16
__device__ __half g_VT[B_*D_*N_];             // [b][e][n]  V transposed, fp16
__device__ float g_epart[B_*SPLITS*D_*D_];    // [b][s][d][e]
__device__ __half g_Q[M_*D_];                 // Q fp16
__device__ __half g_eT[B_*D_*D_];             // [b][v][k] = scale*energy[k][v], fp16
__device__ __half g_C[M_*D_];                 // context fp16
__device__ __half g_Wh[192*E_];               // [n][k] fp16 (exact +-2^-5)
__device__ __half g_Woh[E_*D_];               // [e][v] fp16 (exact +-2^-3)

// ---------------------------------------------------------------------------
// helpers
// ---------------------------------------------------------------------------
// D(16x8,f32) += A(16x16,f16,row) * B(16x8,f16,col)
__device__ __forceinline__ void mma16816h(float* d, const unsigned* a, const unsigned* b) {
    asm volatile(
        "mma.sync.aligned.m16n8k16.row.col.f32.f16.f16.f32 "
        "{%0,%1,%2,%3}, {%4,%5,%6,%7}, {%8,%9}, {%0,%1,%2,%3};\n"
        : "+f"(d[0]), "+f"(d[1]), "+f"(d[2]), "+f"(d[3])
        : "r"(a[0]), "r"(a[1]), "r"(a[2]), "r"(a[3]), "r"(b[0]), "r"(b[1]));
}

__device__ __forceinline__ void ldmx4(unsigned* r, const void* p) {
    unsigned a = (unsigned)__cvta_generic_to_shared(p);
    asm volatile("ldmatrix.sync.aligned.m8n8.x4.shared.b16 {%0,%1,%2,%3}, [%4];"
        : "=r"(r[0]), "=r"(r[1]), "=r"(r[2]), "=r"(r[3]) : "r"(a));
}

// ---------------------------------------------------------------------------
// K0a: pre-convert qkv weights to fp16 (exact: +-2^-5), layout [n][k].
// ---------------------------------------------------------------------------
__global__ __launch_bounds__(256) void wconv_kernel(
    const float* __restrict__ Wq, const float* __restrict__ Wk, const float* __restrict__ Wv)
{
    int i = blockIdx.x * 256 + threadIdx.x;
    int n = i >> 8;
    int g = i & 255;
    const float* W = (n < 64) ? Wq : (n < 128 ? Wk : Wv);
    int rr = n & 63;
    float4 v = *(const float4*)&W[(size_t)rr * E_ + g * 4];
    __half2 p01 = __floats2half2_rn(v.x, v.y);
    __half2 p23 = __floats2half2_rn(v.z, v.w);
    uint2 u; u.x = *(unsigned*)&p01; u.y = *(unsigned*)&p23;
    *(uint2*)&g_Wh[(size_t)n * E_ + g * 4] = u;
}

// K0b: pre-convert wo to fp16 (exact: +-2^-3).  [E][64] row-major.
__global__ __launch_bounds__(256) void woconv_kernel(const float* __restrict__ Wo)
{
    int i = blockIdx.x * 256 + threadIdx.x;
    int r = i >> 4, g = i & 15;
    float4 v = *(const float4*)&Wo[(size_t)r * D_ + g * 4];
    __half2 p01 = __floats2half2_rn(v.x, v.y);
    __half2 p23 = __floats2half2_rn(v.z, v.w);
    uint2 u; u.x = *(unsigned*)&p01; u.y = *(unsigned*)&p23;
    *(uint2*)&g_Woh[(size_t)r * D_ + g * 4] = u;
}

// ---------------------------------------------------------------------------
// K1: fused QKV projection on fp16 MMA, single product, PING-PONG smem
// (1 barrier per chunk; store of chunk c+1 overlaps compute of chunk c).
// BM=64, BN=192, BK=32, 8 warps (2m x 4n), warp tile 32m x 48n.
// Q written fp16 row-major; K,V written fp16 TRANSPOSED ([d][n]) for the
// tensor-core energy kernel.
// ---------------------------------------------------------------------------
__global__ __launch_bounds__(256) void qkv_mma_kernel(const float* __restrict__ X)
{
    __shared__ __half Xs[2][64][40];    // 80B row stride: ldmatrix conflict-free
    __shared__ __half Wb[2][192][40];

    const int m0   = blockIdx.x * 64;
    const int tid  = threadIdx.x;
    const int warp = tid >> 5, lane = tid & 31;
    const int wm = warp >> 2, wn = warp & 3;
    const int lr = lane >> 2, lc = (lane & 3) * 2;

    float acc[2][6][4];
    #pragma unroll
    for (int i = 0; i < 2; i++)
        #pragma unroll
        for (int j = 0; j < 6; j++)
            #pragma unroll
            for (int q = 0; q < 4; q++) acc[i][j][q] = 0.f;

    // chunk 0: load + store into buffer 0
    float4 xv[2];
    uint4  wvb[3];
    #pragma unroll
    for (int t = 0; t < 2; t++) {
        int idx = t * 256 + tid;
        int r = idx >> 3, c = idx & 7;
        xv[t] = *(const float4*)&X[(size_t)(m0 + r) * E_ + c * 4];
    }
    #pragma unroll
    for (int t = 0; t < 3; t++) {
        int idx = t * 256 + tid;
        int r = idx >> 2, q = idx & 3;
        wvb[t] = *(const uint4*)&g_Wh[(size_t)r * E_ + q * 8];
    }
    #pragma unroll
    for (int t = 0; t < 2; t++) {
        int idx = t * 256 + tid;
        int r = idx >> 3, c = idx & 7;
        __half2 p01 = __floats2half2_rn(xv[t].x, xv[t].y);
        __half2 p23 = __floats2half2_rn(xv[t].z, xv[t].w);
        uint2 u; u.x = *(unsigned*)&p01; u.y = *(unsigned*)&p23;
        *(uint2*)&Xs[0][r][c * 4] = u;
    }
    #pragma unroll
    for (int t = 0; t < 3; t++) {
        int idx = t * 256 + tid;
        int r = idx >> 2, q = idx & 3;
        *(uint4*)&Wb[0][r][q * 8] = wvb[t];
    }
    __syncthreads();

    for (int chunk = 0; chunk < 32; chunk++) {
        const int buf = chunk & 1;
        const bool more = (chunk + 1 < 32);

        // issue loads for chunk+1 (in flight during compute)
        if (more) {
            int kn = (chunk + 1) * 32;
            #pragma unroll
            for (int t = 0; t < 2; t++) {
                int idx = t * 256 + tid;
                int r = idx >> 3, c = idx & 7;
                xv[t] = *(const float4*)&X[(size_t)(m0 + r) * E_ + kn + c * 4];
            }
            #pragma unroll
            for (int t = 0; t < 3; t++) {
                int idx = t * 256 + tid;
                int r = idx >> 2, q = idx & 3;
                wvb[t] = *(const uint4*)&g_Wh[(size_t)r * E_ + kn + q * 8];
            }
        }

        // compute chunk from buf
        #pragma unroll
        for (int ks = 0; ks < 32; ks += 16) {
            unsigned bf[6][2];
            #pragma unroll
            for (int np = 0; np < 3; np++) {
                int n0 = wn * 48 + np * 16;
                const __half* p =
                    &Wb[buf][n0 + ((lane >> 4) << 3) + (lane & 7)][ks + (((lane >> 3) & 1) << 3)];
                unsigned t4[4];
                ldmx4(t4, p);
                bf[np*2][0] = t4[0]; bf[np*2][1] = t4[1];
                bf[np*2+1][0] = t4[2]; bf[np*2+1][1] = t4[3];
            }
            #pragma unroll
            for (int mt = 0; mt < 2; mt++) {
                int r0 = wm * 32 + mt * 16;
                unsigned ax[4];
                ldmx4(ax, &Xs[buf][r0 + (lane & 15)][ks + ((lane >> 4) << 3)]);
                #pragma unroll
                for (int nt = 0; nt < 6; nt++) mma16816h(acc[mt][nt], ax, bf[nt]);
            }
        }

        // store chunk+1 into the other buffer (no reader this iteration)
        if (more) {
            const int nb = buf ^ 1;
            #pragma unroll
            for (int t = 0; t < 2; t++) {
                int idx = t * 256 + tid;
                int r = idx >> 3, c = idx & 7;
                __half2 p01 = __floats2half2_rn(xv[t].x, xv[t].y);
                __half2 p23 = __floats2half2_rn(xv[t].z, xv[t].w);
                uint2 u; u.x = *(unsigned*)&p01; u.y = *(unsigned*)&p23;
                *(uint2*)&Xs[nb][r][c * 4] = u;
            }
            #pragma unroll
            for (int t = 0; t < 3; t++) {
                int idx = t * 256 + tid;
                int r = idx >> 2, q = idx & 3;
                *(uint4*)&Wb[nb][r][q * 8] = wvb[t];
            }
            __syncthreads();
        }
    }

    // Epilogue: fragment n-range selects Q / K / V (8 | 64, never crosses)
    #pragma unroll
    for (int mt = 0; mt < 2; mt++)
        #pragma unroll
        for (int nt = 0; nt < 6; nt++) {
            int ng  = wn * 48 + nt * 8;
            int sel = ng >> 6;
            int col = (ng & 63) + lc;
            int row = m0 + wm * 32 + mt * 16 + lr;
            if (sel == 0) {
                __half2 p0 = __floats2half2_rn(acc[mt][nt][0], acc[mt][nt][1]);
                __half2 p1 = __floats2half2_rn(acc[mt][nt][2], acc[mt][nt][3]);
                *(__half2*)&g_Q[(size_t)row * D_ + col] = p0;
                *(__half2*)&g_Q[(size_t)(row + 8) * D_ + col] = p1;
            } else {
                __half* OutT = (sel == 1) ? g_KT : g_VT;
                int bb = row >> 13;              // / N_
                int n  = row & (N_ - 1);
                size_t base = ((size_t)bb * D_ + col) * N_;
                OutT[base + n]          = __float2half_rn(acc[mt][nt][0]);
                OutT[base + N_ + n]     = __float2half_rn(acc[mt][nt][1]);
                OutT[base + n + 8]      = __float2half_rn(acc[mt][nt][2]);
                OutT[base + N_ + n + 8] = __float2half_rn(acc[mt][nt][3]);
            }
        }
}

// ---------------------------------------------------------------------------
// K2: energy partials on tensor cores.  epart[b][s][d][e] over 128 n-rows.
// A = KT[d][n] (row-major frags), B = VT[e][n] (col-major frags) — both use
// the proven non-transposed ldmatrix patterns.  8 warps (2m x 4n),
// warp tile 32d x 16e, single smem fill, 8 k-steps.
// ---------------------------------------------------------------------------
__global__ __launch_bounds__(256) void energy_kernel()
{
    __shared__ __half KTs[64][136];   // 272B row stride (17*16B): conflict-free
    __shared__ __half VTs[64][136];

    const int s = blockIdx.x;
    const int b = blockIdx.y;
    const int n_base = s * ROWS_PER_SPLIT;
    const __half* KT = g_KT + (size_t)b * D_ * N_;
    const __half* VT = g_VT + (size_t)b * D_ * N_;

    const int tid  = threadIdx.x;
    const int warp = tid >> 5, lane = tid & 31;
    const int wm = warp >> 2, wn = warp & 3;
    const int lr = lane >> 2, lc = (lane & 3) * 2;

    // fill: 64 rows x 128 halves = 16 uint4 per row, 1024 per matrix (4/thr)
    #pragma unroll
    for (int t = 0; t < 4; t++) {
        int idx = t * 256 + tid;
        int r = idx >> 4, c8 = idx & 15;
        *(uint4*)&KTs[r][c8 * 8] = *(const uint4*)&KT[(size_t)r * N_ + n_base + c8 * 8];
        *(uint4*)&VTs[r][c8 * 8] = *(const uint4*)&VT[(size_t)r * N_ + n_base + c8 * 8];
    }
    __syncthreads();

    float acc[2][2][4];
    #pragma unroll
    for (int i = 0; i < 2; i++)
        #pragma unroll
        for (int j = 0; j < 2; j++)
            #pragma unroll
            for (int q = 0; q < 4; q++) acc[i][j][q] = 0.f;

    #pragma unroll
    for (int ks = 0; ks < ROWS_PER_SPLIT; ks += 16) {
        unsigned bv[2][2];
        {
            int nrow = wn * 16 + ((lane >> 4) << 3) + (lane & 7);
            int ncol = ks + (((lane >> 3) & 1) << 3);
            unsigned t4[4];
            ldmx4(t4, &VTs[nrow][ncol]);
            bv[0][0] = t4[0]; bv[0][1] = t4[1];
            bv[1][0] = t4[2]; bv[1][1] = t4[3];
        }
        #pragma unroll
        for (int mt = 0; mt < 2; mt++) {
            int r0 = wm * 32 + mt * 16;
            unsigned ak[4];
            ldmx4(ak, &KTs[r0 + (lane & 15)][ks + ((lane >> 4) << 3)]);
            mma16816h(acc[mt][0], ak, bv[0]);
            mma16816h(acc[mt][1], ak, bv[1]);
        }
    }

    float* ep = g_epart + ((size_t)(b * SPLITS + s)) * (D_ * D_);
    #pragma unroll
    for (int mt = 0; mt < 2; mt++)
        #pragma unroll
        for (int nt = 0; nt < 2; nt++) {
            int row = wm * 32 + mt * 16 + lr;
            int col = wn * 16 + nt * 8 + lc;
            *(float2*)&ep[row * D_ + col] =
                make_float2(acc[mt][nt][0], acc[mt][nt][1]);
            *(float2*)&ep[(row + 8) * D_ + col] =
                make_float2(acc[mt][nt][2], acc[mt][nt][3]);
        }
}

// ---------------------------------------------------------------------------
// K3: reduce epart over 64 splits -> scaled eT[v][k] in fp16.
// ---------------------------------------------------------------------------
__global__ __launch_bounds__(256) void ereduce_kernel()
{
    const int b = blockIdx.y;
    const int base = blockIdx.x * 256 + threadIdx.x;   // 0..4095 = k*64+v
    const float* ep = g_epart + (size_t)b * SPLITS * D_ * D_ + base;
    float s = 0.f;
    #pragma unroll
    for (int sp = 0; sp < SPLITS; sp++)
        s += ep[(size_t)sp * (D_ * D_)];
    s *= SCALE_;
    int k = base >> 6;
    int v = base & 63;
    g_eT[(size_t)b * D_ * D_ + v * D_ + k] = __float2half_rn(s);
}

// ---------------------------------------------------------------------------
// K4: context[m][v] = sum_k Q[m][k] * (scale*energy)[k][v], fp16 single product.
// BM=128, BN=64, BK=32.  8 warps (4m x 2n).  Writes context fp16.
// ---------------------------------------------------------------------------
__global__ __launch_bounds__(256) void context_kernel()
{
    __shared__ __half Qs[128][40];
    __shared__ __half Es[64][40];

    const int m0 = blockIdx.x * 128;
    const int b  = m0 >> 13;
    const size_t eb = (size_t)b * D_ * D_;
    const int tid  = threadIdx.x;
    const int warp = tid >> 5, lane = tid & 31;
    const int wm = warp >> 1, wn = warp & 1;
    const int lr = lane >> 2, lc = (lane & 3) * 2;

    float acc[2][4][4];
    #pragma unroll
    for (int i = 0; i < 2; i++)
        #pragma unroll
        for (int j = 0; j < 4; j++)
            #pragma unroll
            for (int q = 0; q < 4; q++) acc[i][j][q] = 0.f;

    for (int k0 = 0; k0 < D_; k0 += 32) {
        #pragma unroll
        for (int t = 0; t < 4; t++) {
            int idx = t * 256 + tid;
            int r = idx >> 3, c = idx & 7;
            *(uint2*)&Qs[r][c * 4] = *(const uint2*)&g_Q[(size_t)(m0 + r) * D_ + k0 + c * 4];
        }
        #pragma unroll
        for (int t = 0; t < 2; t++) {
            int idx = t * 256 + tid;
            int r = idx >> 3, c = idx & 7;
            *(uint2*)&Es[r][c * 4] = *(const uint2*)&g_eT[eb + (size_t)r * D_ + k0 + c * 4];
        }
        __syncthreads();

        #pragma unroll
        for (int ks = 0; ks < 32; ks += 16) {
            unsigned be[4][2];
            #pragma unroll
            for (int np = 0; np < 2; np++) {
                int nrow = wn * 32 + np * 16 + ((lane >> 4) << 3) + (lane & 7);
                int ncol = ks + (((lane >> 3) & 1) << 3);
                unsigned t4[4];
                ldmx4(t4, &Es[nrow][ncol]);
                be[np*2][0] = t4[0]; be[np*2][1] = t4[1];
                be[np*2+1][0] = t4[2]; be[np*2+1][1] = t4[3];
            }
            #pragma unroll
            for (int mt = 0; mt < 2; mt++) {
                int r0 = wm * 32 + mt * 16;
                unsigned aq[4];
                ldmx4(aq, &Qs[r0 + (lane & 15)][ks + ((lane >> 4) << 3)]);
                #pragma unroll
                for (int nt = 0; nt < 4; nt++) mma16816h(acc[mt][nt], aq, be[nt]);
            }
        }
        __syncthreads();
    }

    #pragma unroll
    for (int mt = 0; mt < 2; mt++)
        #pragma unroll
        for (int nt = 0; nt < 4; nt++) {
            int row = m0 + wm * 32 + mt * 16 + lr;
            int col = wn * 32 + nt * 8 + lc;
            __half2 p0 = __floats2half2_rn(acc[mt][nt][0], acc[mt][nt][1]);
            __half2 p1 = __floats2half2_rn(acc[mt][nt][2], acc[mt][nt][3]);
            *(__half2*)&g_C[(size_t)row * D_ + col] = p0;
            *(__half2*)&g_C[(size_t)(row + 8) * D_ + col] = p1;
        }
}

// ---------------------------------------------------------------------------
// K5: out[b][m][e] = sum_v context[m][v] * wo[e][v], fp16 single product.
// BM=128, BN=128, BK=32, 8 warps (4m x 2n), warp tile 32m x 64n.
// ---------------------------------------------------------------------------
__global__ __launch_bounds__(256) void out_mma_kernel(float* __restrict__ Out)
{
    __shared__ __half Cs[128][40];
    __shared__ __half Ws[128][40];

    const int m0 = blockIdx.x * 128;
    const int e0 = blockIdx.y * 128;
    const int b  = blockIdx.z;
    const int tid  = threadIdx.x;
    const int warp = tid >> 5, lane = tid & 31;
    const int wm = warp >> 1, wn = warp & 1;
    const int lr = lane >> 2, lc = (lane & 3) * 2;

    const size_t cbase = ((size_t)b * N_ + m0) * D_;

    float acc[2][8][4];
    #pragma unroll
    for (int i = 0; i < 2; i++)
        #pragma unroll
        for (int j = 0; j < 8; j++)
            #pragma unroll
            for (int q = 0; q < 4; q++) acc[i][j][q] = 0.f;

    uint2 cv[4], wv[4];
    #pragma unroll
    for (int t = 0; t < 4; t++) {
        int idx = t * 256 + tid;
        int r = idx >> 3, c = idx & 7;
        cv[t] = *(const uint2*)&g_C[cbase + (size_t)r * D_ + c * 4];
        wv[t] = *(const uint2*)&g_Woh[(size_t)(e0 + r) * D_ + c * 4];
    }

    for (int k0 = 0; k0 < D_; k0 += 32) {
        #pragma unroll
        for (int t = 0; t < 4; t++) {
            int idx = t * 256 + tid;
            int r = idx >> 3, c = idx & 7;
            *(uint2*)&Cs[r][c * 4] = cv[t];
            *(uint2*)&Ws[r][c * 4] = wv[t];
        }
        __syncthreads();

        if (k0 + 32 < D_) {
            int kn = k0 + 32;
            #pragma unroll
            for (int t = 0; t < 4; t++) {
                int idx = t * 256 + tid;
                int r = idx >> 3, c = idx & 7;
                cv[t] = *(const uint2*)&g_C[cbase + (size_t)r * D_ + kn + c * 4];
                wv[t] = *(const uint2*)&g_Woh[(size_t)(e0 + r) * D_ + kn + c * 4];
            }
        }

        #pragma unroll
        for (int ks = 0; ks < 32; ks += 16) {
            unsigned bw[8][2];
            #pragma unroll
            for (int np = 0; np < 4; np++) {
                int nrow = wn * 64 + np * 16 + ((lane >> 4) << 3) + (lane & 7);
                int ncol = ks + (((lane >> 3) & 1) << 3);
                unsigned t4[4];
                ldmx4(t4, &Ws[nrow][ncol]);
                bw[np*2][0] = t4[0]; bw[np*2][1] = t4[1];
                bw[np*2+1][0] = t4[2]; bw[np*2+1][1] = t4[3];
            }
            #pragma unroll
            for (int mt = 0; mt < 2; mt++) {
                int r0 = wm * 32 + mt * 16;
                unsigned ac[4];
                ldmx4(ac, &Cs[r0 + (lane & 15)][ks + ((lane >> 4) << 3)]);
                #pragma unroll
                for (int nt = 0; nt < 8; nt++) mma16816h(acc[mt][nt], ac, bw[nt]);
            }
        }
        __syncthreads();
    }

    #pragma unroll
    for (int mt = 0; mt < 2; mt++)
        #pragma unroll
        for (int nt = 0; nt < 8; nt++) {
            int row = m0 + wm * 32 + mt * 16 + lr;
            int col = e0 + wn * 64 + nt * 8 + lc;
            *(float2*)&Out[((size_t)b * N_ + row) * E_ + col] =
                make_float2(acc[mt][nt][0], acc[mt][nt][1]);
            *(float2*)&Out[((size_t)b * N_ + row + 8) * E_ + col] =
                make_float2(acc[mt][nt][2], acc[mt][nt][3]);
        }
}

// ---------------------------------------------------------------------------
extern "C" void kernel_launch(void* const* d_in, const int* in_sizes, int n_in,
                              void* d_out, int out_size)
{
    const float* x  = (const float*)d_in[0];
    const float* wq = (const float*)d_in[1];
    const float* wk = (const float*)d_in[2];
    const float* wv = (const float*)d_in[3];
    const float* wo = (const float*)d_in[4];
    float* out = (float*)d_out;

    wconv_kernel  <<<192 * 1024 / 4 / 256, 256>>>(wq, wk, wv);
    woconv_kernel <<<E_ * D_ / 4 / 256, 256>>>(wo);
    qkv_mma_kernel<<<M_ / 64, 256>>>(x);
    energy_kernel <<<dim3(SPLITS, B_), 256>>>();
    ereduce_kernel<<<dim3(16, B_), 256>>>();
    context_kernel<<<M_ / 128, 256>>>();
    out_mma_kernel<<<dim3(N_ / 128, E_ / 128, B_), 256>>>(out);
}